// round 1
// baseline (speedup 1.0000x reference)
#include <cuda_runtime.h>

#define NN 100000
#define EE 260000
#define DD 300
#define D4 75          // DD/4
#define LL 5
#define GG 4096
#define BN_EPS 1e-5f

// ---------------- scratch (device globals; no allocation allowed) ----------
__device__ __align__(16) float g_h  [(size_t)NN * DD];
__device__ __align__(16) float g_e  [(size_t)EE * DD];
__device__ __align__(16) float g_agg[(size_t)NN * DD];
__device__ __align__(16) float g_tmp[(size_t)EE * DD];   // reused: node tmp (N<=E) & layer tmp
__device__ __align__(16) float g_out[(size_t)NN * DD];
__device__             float g_stats[2 * DD];
__device__ __align__(16) float g_pool[(size_t)GG * DD];
__device__             float g_cnt [GG];

// ---------------- elementwise preambles ------------------------------------
__global__ void node_pre_k(const float* __restrict__ chi, const float* __restrict__ fc,
                           const float* __restrict__ w1, const float* __restrict__ b1) {
    int idx = blockIdx.x * blockDim.x + threadIdx.x;
    if (idx >= NN * DD) return;
    int n = idx / DD, d = idx - n * DD;
    float v = chi[n] * w1[d] + fc[n] * w1[DD + d] + b1[d];
    g_tmp[idx] = fmaxf(v, 0.f);
}

__global__ void edge_pre_k(const float* __restrict__ ea,
                           const float* __restrict__ w1, const float* __restrict__ b1) {
    int idx = blockIdx.x * blockDim.x + threadIdx.x;
    if (idx >= EE * DD) return;
    int e = idx / DD, d = idx - e * DD;
    float v = ea[e * 3 + 0] * w1[d] + ea[e * 3 + 1] * w1[DD + d]
            + ea[e * 3 + 2] * w1[2 * DD + d] + b1[d];
    g_tmp[idx] = fmaxf(v, 0.f);
}

// ---------------- SGEMM: C[m,n] = act(A[m,:300] @ W[300,n] + bias[n] (+ gather)) ----
__global__ __launch_bounds__(256)
void gemm300_k(const float* __restrict__ A, const float* __restrict__ W,
               const float* __restrict__ bias, float* __restrict__ C,
               float* __restrict__ C2, int M, int relu,
               const float* __restrict__ gtab, const int* __restrict__ gidx) {
    __shared__ float As[16][65];
    __shared__ float Bs[16][65];
    int t  = threadIdx.x;
    int tx = t & 15, ty = t >> 4;
    int m0 = blockIdx.y * 64, n0 = blockIdx.x * 64;
    float acc[4][4] = {};

    for (int k0 = 0; k0 < DD; k0 += 16) {
        #pragma unroll
        for (int i = 0; i < 4; i++) {
            int m = (t >> 4) + i * 16;
            int k = t & 15;
            int gm = m0 + m, gk = k0 + k;
            As[k][m] = (gm < M && gk < DD) ? A[(size_t)gm * DD + gk] : 0.f;
        }
        #pragma unroll
        for (int i = 0; i < 4; i++) {
            int k = (t >> 6) + i * 4;
            int n = t & 63;
            int gk = k0 + k, gn = n0 + n;
            Bs[k][n] = (gk < DD && gn < DD) ? W[(size_t)gk * DD + gn] : 0.f;
        }
        __syncthreads();
        #pragma unroll
        for (int k = 0; k < 16; k++) {
            float a[4], b[4];
            #pragma unroll
            for (int i = 0; i < 4; i++) a[i] = As[k][ty * 4 + i];
            #pragma unroll
            for (int j = 0; j < 4; j++) b[j] = Bs[k][tx * 4 + j];
            #pragma unroll
            for (int i = 0; i < 4; i++)
                #pragma unroll
                for (int j = 0; j < 4; j++)
                    acc[i][j] += a[i] * b[j];
        }
        __syncthreads();
    }

    #pragma unroll
    for (int i = 0; i < 4; i++) {
        int gm = m0 + ty * 4 + i;
        if (gm >= M) continue;
        int gz = (gidx != nullptr) ? gidx[gm] : 0;
        #pragma unroll
        for (int j = 0; j < 4; j++) {
            int gn = n0 + tx * 4 + j;
            if (gn >= DD) continue;
            float v = acc[i][j] + bias[gn];
            if (gtab != nullptr) v += gtab[(size_t)gz * DD + gn];
            if (relu) v = fmaxf(v, 0.f);
            C[(size_t)gm * DD + gn] = v;
            if (C2 != nullptr) C2[(size_t)gm * DD + gn] = v;
        }
    }
}

// ---------------- message + scatter-add (agg preloaded with h) --------------
__global__ void msg_k(const int* __restrict__ ei) {
    int idx = blockIdx.x * blockDim.x + threadIdx.x;
    if (idx >= EE * D4) return;
    int e = idx / D4, j = idx - e * D4;
    int s = ei[e];
    int d = ei[EE + e];
    float4 hv = reinterpret_cast<const float4*>(g_h)[(size_t)s * D4 + j];
    float4 ev = reinterpret_cast<const float4*>(g_e)[(size_t)e * D4 + j];
    float x0 = fmaxf(hv.x + ev.x, 0.f);
    float x1 = fmaxf(hv.y + ev.y, 0.f);
    float x2 = fmaxf(hv.z + ev.z, 0.f);
    float x3 = fmaxf(hv.w + ev.w, 0.f);
    float* base = &g_agg[(size_t)d * DD + j * 4];
    atomicAdd(base + 0, x0);
    atomicAdd(base + 1, x1);
    atomicAdd(base + 2, x2);
    atomicAdd(base + 3, x3);
}

// ---------------- batchnorm --------------------------------------------------
__global__ void zero_stats_k() {
    int i = threadIdx.x;
    if (i < 2 * DD) g_stats[i] = 0.f;
}

#define BN_ROWS 512
__global__ void bn_stats_k() {
    int d = threadIdx.x;
    if (d >= DD) return;
    int r0 = blockIdx.x * BN_ROWS;
    int r1 = r0 + BN_ROWS; if (r1 > NN) r1 = NN;
    float s = 0.f, s2 = 0.f;
    int r = r0;
    for (; r + 4 <= r1; r += 4) {
        float v0 = g_out[(size_t)(r + 0) * DD + d];
        float v1 = g_out[(size_t)(r + 1) * DD + d];
        float v2 = g_out[(size_t)(r + 2) * DD + d];
        float v3 = g_out[(size_t)(r + 3) * DD + d];
        s  += (v0 + v1) + (v2 + v3);
        s2 += (v0 * v0 + v1 * v1) + (v2 * v2 + v3 * v3);
    }
    for (; r < r1; r++) {
        float v = g_out[(size_t)r * DD + d];
        s += v; s2 += v * v;
    }
    atomicAdd(&g_stats[d], s);
    atomicAdd(&g_stats[DD + d], s2);
}

__global__ void bn_apply_k(const float* __restrict__ gamma, const float* __restrict__ beta) {
    int idx = blockIdx.x * blockDim.x + threadIdx.x;
    if (idx >= NN * DD) return;
    int d = idx % DD;
    const float invN = 1.f / (float)NN;
    float mean = g_stats[d] * invN;
    float var  = g_stats[DD + d] * invN - mean * mean;
    float v = gamma[d] * (g_out[idx] - mean) * rsqrtf(var + BN_EPS) + beta[d];
    v = fmaxf(v, 0.f);
    g_h[idx]   = v;
    g_agg[idx] = v;   // pre-seed next layer's aggregate with h (GINE: h + sum msgs)
}

// ---------------- pooling ----------------------------------------------------
__global__ void pool_zero_k() {
    int idx = blockIdx.x * blockDim.x + threadIdx.x;
    if (idx < GG * DD) g_pool[idx] = 0.f;
    if (idx < GG) g_cnt[idx] = 0.f;
}

__global__ void pool_acc_k(const int* __restrict__ batch) {
    int idx = blockIdx.x * blockDim.x + threadIdx.x;
    if (idx >= NN * D4) return;
    int n = idx / D4, j = idx - n * D4;
    int g = batch[n];
    float4 v = reinterpret_cast<const float4*>(g_h)[(size_t)n * D4 + j];
    float* base = &g_pool[(size_t)g * DD + j * 4];
    atomicAdd(base + 0, v.x);
    atomicAdd(base + 1, v.y);
    atomicAdd(base + 2, v.z);
    atomicAdd(base + 3, v.w);
}

__global__ void pool_cnt_k(const int* __restrict__ batch) {
    int n = blockIdx.x * blockDim.x + threadIdx.x;
    if (n >= NN) return;
    atomicAdd(&g_cnt[batch[n]], 1.f);
}

__global__ void pool_div_k() {
    int idx = blockIdx.x * blockDim.x + threadIdx.x;
    if (idx >= GG * DD) return;
    int g = idx / DD;
    float c = g_cnt[g];
    g_pool[idx] = (c > 0.f) ? g_pool[idx] / c : 0.f;
}

// ---------------- launch -----------------------------------------------------
static inline int cdiv(int a, int b) { return (a + b - 1) / b; }

extern "C" void kernel_launch(void* const* d_in, const int* in_sizes, int n_in,
                              void* d_out, int out_size) {
    const int*   z        = (const int*)  d_in[0];
    const float* chi      = (const float*)d_in[1];
    const float* fc       = (const float*)d_in[2];
    const int*   ei       = (const int*)  d_in[3];
    const float* ea       = (const float*)d_in[4];
    const int*   batch    = (const int*)  d_in[5];
    const float* atom_emb = (const float*)d_in[6];
    const float* nap_w1   = (const float*)d_in[7];
    const float* nap_b1   = (const float*)d_in[8];
    const float* nap_w2   = (const float*)d_in[9];
    const float* nap_b2   = (const float*)d_in[10];
    const float* ee_w1    = (const float*)d_in[11];
    const float* ee_b1    = (const float*)d_in[12];
    const float* ee_w2    = (const float*)d_in[13];
    const float* ee_b2    = (const float*)d_in[14];
    const float* mlp_w1   = (const float*)d_in[15];
    const float* mlp_b1   = (const float*)d_in[16];
    const float* mlp_w2   = (const float*)d_in[17];
    const float* mlp_b2   = (const float*)d_in[18];
    const float* bn_gamma = (const float*)d_in[19];
    const float* bn_beta  = (const float*)d_in[20];
    const float* pool_w   = (const float*)d_in[21];
    const float* pool_b   = (const float*)d_in[22];
    float* out = (float*)d_out;

    float *ph, *pe, *pagg, *ptmp, *pout, *ppool;
    cudaGetSymbolAddress((void**)&ph,    g_h);
    cudaGetSymbolAddress((void**)&pe,    g_e);
    cudaGetSymbolAddress((void**)&pagg,  g_agg);
    cudaGetSymbolAddress((void**)&ptmp,  g_tmp);
    cudaGetSymbolAddress((void**)&pout,  g_out);
    cudaGetSymbolAddress((void**)&ppool, g_pool);

    const int TPB = 256;
    dim3 gemm_grid_N(cdiv(DD, 64), cdiv(NN, 64));
    dim3 gemm_grid_E(cdiv(DD, 64), cdiv(EE, 64));
    dim3 gemm_grid_G(cdiv(DD, 64), cdiv(GG, 64));

    // ---- node features: h0 = atom_emb[z] + MLP(node_attr); also seed agg = h0
    node_pre_k<<<cdiv(NN * DD, TPB), TPB>>>(chi, fc, nap_w1, nap_b1);
    gemm300_k<<<gemm_grid_N, 256>>>(ptmp, nap_w2, nap_b2, ph, pagg, NN, 0, atom_emb, z);

    // ---- edge features: e = MLP(edge_attr)
    edge_pre_k<<<cdiv(EE * DD, TPB), TPB>>>(ea, ee_w1, ee_b1);
    gemm300_k<<<gemm_grid_E, 256>>>(ptmp, ee_w2, ee_b2, pe, nullptr, EE, 0, nullptr, nullptr);

    // ---- L GINE layers
    for (int l = 0; l < LL; l++) {
        // agg already = h (seeded by prior epilogue); add sum_j relu(h[src]+e)
        msg_k<<<cdiv(EE * D4, TPB), TPB>>>(ei);
        gemm300_k<<<gemm_grid_N, 256>>>(pagg, mlp_w1 + (size_t)l * DD * DD, mlp_b1 + l * DD,
                                        ptmp, nullptr, NN, 1, nullptr, nullptr);
        gemm300_k<<<gemm_grid_N, 256>>>(ptmp, mlp_w2 + (size_t)l * DD * DD, mlp_b2 + l * DD,
                                        pout, nullptr, NN, 0, nullptr, nullptr);
        zero_stats_k<<<1, 2 * DD>>>();
        bn_stats_k<<<cdiv(NN, BN_ROWS), 320>>>();
        bn_apply_k<<<cdiv(NN * DD, TPB), TPB>>>(bn_gamma + l * DD, bn_beta + l * DD);
    }

    // ---- mean pool per graph + final projection
    pool_zero_k<<<cdiv(GG * DD, TPB), TPB>>>();
    pool_acc_k<<<cdiv(NN * D4, TPB), TPB>>>(batch);
    pool_cnt_k<<<cdiv(NN, TPB), TPB>>>(batch);
    pool_div_k<<<cdiv(GG * DD, TPB), TPB>>>();
    gemm300_k<<<gemm_grid_G, 256>>>(ppool, pool_w, pool_b, out, nullptr, GG, 0, nullptr, nullptr);
}

// round 2
// speedup vs baseline: 1.4568x; 1.4568x over previous
#include <cuda_runtime.h>

#define NN 100000
#define EE 260000
#define DD 300
#define D4 75          // DD/4
#define LL 5
#define GG 4096
#define BN_EPS 1e-5f

// ---------------- scratch (device globals; no allocation allowed) ----------
__device__ __align__(16) float g_h  [(size_t)NN * DD];
__device__ __align__(16) float g_e  [(size_t)EE * DD];
__device__ __align__(16) float g_agg[(size_t)NN * DD];
__device__ __align__(16) float g_tmp[(size_t)EE * DD];   // reused: node tmp (N<=E) & layer tmp
__device__ __align__(16) float g_out[(size_t)NN * DD];
__device__             float g_stats[2 * DD];
__device__ __align__(16) float g_pool[(size_t)GG * DD];
__device__             float g_cnt [GG];

// ---------------- elementwise preambles ------------------------------------
__global__ void node_pre_k(const float* __restrict__ chi, const float* __restrict__ fc,
                           const float* __restrict__ w1, const float* __restrict__ b1) {
    int idx = blockIdx.x * blockDim.x + threadIdx.x;
    if (idx >= NN * DD) return;
    int n = idx / DD, d = idx - n * DD;
    float v = chi[n] * w1[d] + fc[n] * w1[DD + d] + b1[d];
    g_tmp[idx] = fmaxf(v, 0.f);
}

__global__ void edge_pre_k(const float* __restrict__ ea,
                           const float* __restrict__ w1, const float* __restrict__ b1) {
    int idx = blockIdx.x * blockDim.x + threadIdx.x;
    if (idx >= EE * DD) return;
    int e = idx / DD, d = idx - e * DD;
    float v = ea[e * 3 + 0] * w1[d] + ea[e * 3 + 1] * w1[DD + d]
            + ea[e * 3 + 2] * w1[2 * DD + d] + b1[d];
    g_tmp[idx] = fmaxf(v, 0.f);
}

// ---------------- SGEMM: C[m,n] = act(A[m,:300] @ W[300,n] + bias[n] (+ gather)) ----
// BM=128, BN=64, BK=16; 256 threads; 8x4 outputs/thread; double-buffered smem.
#define BM 128
#define BN 64
#define BK 16
#define KT 19          // ceil(300/16)

__global__ __launch_bounds__(256)
void gemm300_k(const float* __restrict__ A, const float* __restrict__ W,
               const float* __restrict__ bias, float* __restrict__ C,
               float* __restrict__ C2, int M, int relu,
               const float* __restrict__ gtab, const int* __restrict__ gidx) {
    __shared__ float As[2][BK][132];   // transposed A tile, padded
    __shared__ float Bs[2][BK][68];    // B tile, padded

    const int t  = threadIdx.x;
    const int tx = t & 15;             // N index (x4)
    const int ty = t >> 4;             // M index (x8)
    const int m0 = blockIdx.y * BM;
    const int n0 = blockIdx.x * BN;

    // A-tile load mapping: 128 rows x 16 k; thread covers (row=t>>2 [+64]), k-group=(t&3)*4
    const int ar = t >> 2;
    const int ag = (t & 3) << 2;
    // B-tile load mapping: 16 k x 64 n; thread covers k=t>>4, n=(t&15)*4
    const int bk = t >> 4;
    const int bn = (t & 15) << 2;

    const float4 fz = make_float4(0.f, 0.f, 0.f, 0.f);
    float4 aR0, aR1, bR;

    // ---- prologue: load k-tile 0
    {
        int gm0 = m0 + ar, gm1 = m0 + ar + 64, gk = ag;
        aR0 = (gm0 < M) ? *(const float4*)&A[(size_t)gm0 * DD + gk] : fz;
        aR1 = (gm1 < M) ? *(const float4*)&A[(size_t)gm1 * DD + gk] : fz;
        int gn = n0 + bn;
        bR  = (gn < DD) ? *(const float4*)&W[(size_t)bk * DD + gn] : fz;
    }
    As[0][ag + 0][ar] = aR0.x; As[0][ag + 1][ar] = aR0.y;
    As[0][ag + 2][ar] = aR0.z; As[0][ag + 3][ar] = aR0.w;
    As[0][ag + 0][ar + 64] = aR1.x; As[0][ag + 1][ar + 64] = aR1.y;
    As[0][ag + 2][ar + 64] = aR1.z; As[0][ag + 3][ar + 64] = aR1.w;
    *(float4*)&Bs[0][bk][bn] = bR;
    __syncthreads();

    float acc[8][4] = {};

    for (int tt = 0; tt < KT; tt++) {
        const int buf = tt & 1;
        // prefetch next tile into registers
        if (tt + 1 < KT) {
            int k0 = (tt + 1) * BK;
            int gm0 = m0 + ar, gm1 = m0 + ar + 64, gk = k0 + ag;
            aR0 = (gm0 < M && gk < DD) ? *(const float4*)&A[(size_t)gm0 * DD + gk] : fz;
            aR1 = (gm1 < M && gk < DD) ? *(const float4*)&A[(size_t)gm1 * DD + gk] : fz;
            int gkb = k0 + bk, gn = n0 + bn;
            bR  = (gkb < DD && gn < DD) ? *(const float4*)&W[(size_t)gkb * DD + gn] : fz;
        }
        // compute on current buffer
        #pragma unroll
        for (int k = 0; k < BK; k++) {
            float4 a0 = *(const float4*)&As[buf][k][ty * 8];
            float4 a1 = *(const float4*)&As[buf][k][ty * 8 + 4];
            float4 bv = *(const float4*)&Bs[buf][k][tx * 4];
            float a[8] = {a0.x, a0.y, a0.z, a0.w, a1.x, a1.y, a1.z, a1.w};
            float b[4] = {bv.x, bv.y, bv.z, bv.w};
            #pragma unroll
            for (int i = 0; i < 8; i++)
                #pragma unroll
                for (int j = 0; j < 4; j++)
                    acc[i][j] += a[i] * b[j];
        }
        // store next tile to the other buffer
        if (tt + 1 < KT) {
            const int nb = buf ^ 1;
            As[nb][ag + 0][ar] = aR0.x; As[nb][ag + 1][ar] = aR0.y;
            As[nb][ag + 2][ar] = aR0.z; As[nb][ag + 3][ar] = aR0.w;
            As[nb][ag + 0][ar + 64] = aR1.x; As[nb][ag + 1][ar + 64] = aR1.y;
            As[nb][ag + 2][ar + 64] = aR1.z; As[nb][ag + 3][ar + 64] = aR1.w;
            *(float4*)&Bs[nb][bk][bn] = bR;
            __syncthreads();
        }
    }

    // ---- epilogue
    const int gn = n0 + tx * 4;
    if (gn >= DD) return;
    float4 bv = *(const float4*)&bias[gn];
    #pragma unroll
    for (int i = 0; i < 8; i++) {
        int gm = m0 + ty * 8 + i;
        if (gm >= M) break;
        float4 v = make_float4(acc[i][0] + bv.x, acc[i][1] + bv.y,
                               acc[i][2] + bv.z, acc[i][3] + bv.w);
        if (gtab != nullptr) {
            int gz = gidx[gm];
            float4 g = *(const float4*)&gtab[(size_t)gz * DD + gn];
            v.x += g.x; v.y += g.y; v.z += g.z; v.w += g.w;
        }
        if (relu) {
            v.x = fmaxf(v.x, 0.f); v.y = fmaxf(v.y, 0.f);
            v.z = fmaxf(v.z, 0.f); v.w = fmaxf(v.w, 0.f);
        }
        *(float4*)&C[(size_t)gm * DD + gn] = v;
        if (C2 != nullptr) *(float4*)&C2[(size_t)gm * DD + gn] = v;
    }
}

// ---------------- message + scatter-add (agg preloaded with h) --------------
__global__ void msg_k(const int* __restrict__ ei) {
    int idx = blockIdx.x * blockDim.x + threadIdx.x;
    if (idx >= EE * D4) return;
    int e = idx / D4, j = idx - e * D4;
    int s = ei[e];
    int d = ei[EE + e];
    float4 hv = reinterpret_cast<const float4*>(g_h)[(size_t)s * D4 + j];
    float4 ev = reinterpret_cast<const float4*>(g_e)[(size_t)e * D4 + j];
    float x0 = fmaxf(hv.x + ev.x, 0.f);
    float x1 = fmaxf(hv.y + ev.y, 0.f);
    float x2 = fmaxf(hv.z + ev.z, 0.f);
    float x3 = fmaxf(hv.w + ev.w, 0.f);
    float* base = &g_agg[(size_t)d * DD + j * 4];
    atomicAdd(base + 0, x0);
    atomicAdd(base + 1, x1);
    atomicAdd(base + 2, x2);
    atomicAdd(base + 3, x3);
}

// ---------------- batchnorm --------------------------------------------------
__global__ void zero_stats_k() {
    int i = threadIdx.x;
    if (i < 2 * DD) g_stats[i] = 0.f;
}

#define BN_ROWS 512
__global__ void bn_stats_k() {
    int d = threadIdx.x;
    if (d >= DD) return;
    int r0 = blockIdx.x * BN_ROWS;
    int r1 = r0 + BN_ROWS; if (r1 > NN) r1 = NN;
    float s = 0.f, s2 = 0.f;
    int r = r0;
    for (; r + 4 <= r1; r += 4) {
        float v0 = g_out[(size_t)(r + 0) * DD + d];
        float v1 = g_out[(size_t)(r + 1) * DD + d];
        float v2 = g_out[(size_t)(r + 2) * DD + d];
        float v3 = g_out[(size_t)(r + 3) * DD + d];
        s  += (v0 + v1) + (v2 + v3);
        s2 += (v0 * v0 + v1 * v1) + (v2 * v2 + v3 * v3);
    }
    for (; r < r1; r++) {
        float v = g_out[(size_t)r * DD + d];
        s += v; s2 += v * v;
    }
    atomicAdd(&g_stats[d], s);
    atomicAdd(&g_stats[DD + d], s2);
}

__global__ void bn_apply_k(const float* __restrict__ gamma, const float* __restrict__ beta) {
    int idx = blockIdx.x * blockDim.x + threadIdx.x;
    if (idx >= NN * DD) return;
    int d = idx % DD;
    const float invN = 1.f / (float)NN;
    float mean = g_stats[d] * invN;
    float var  = g_stats[DD + d] * invN - mean * mean;
    float v = gamma[d] * (g_out[idx] - mean) * rsqrtf(var + BN_EPS) + beta[d];
    v = fmaxf(v, 0.f);
    g_h[idx]   = v;
    g_agg[idx] = v;   // pre-seed next layer's aggregate with h (GINE: h + sum msgs)
}

// ---------------- pooling ----------------------------------------------------
__global__ void pool_zero_k() {
    int idx = blockIdx.x * blockDim.x + threadIdx.x;
    if (idx < GG * DD) g_pool[idx] = 0.f;
    if (idx < GG) g_cnt[idx] = 0.f;
}

__global__ void pool_acc_k(const int* __restrict__ batch) {
    int idx = blockIdx.x * blockDim.x + threadIdx.x;
    if (idx >= NN * D4) return;
    int n = idx / D4, j = idx - n * D4;
    int g = batch[n];
    float4 v = reinterpret_cast<const float4*>(g_h)[(size_t)n * D4 + j];
    float* base = &g_pool[(size_t)g * DD + j * 4];
    atomicAdd(base + 0, v.x);
    atomicAdd(base + 1, v.y);
    atomicAdd(base + 2, v.z);
    atomicAdd(base + 3, v.w);
}

__global__ void pool_cnt_k(const int* __restrict__ batch) {
    int n = blockIdx.x * blockDim.x + threadIdx.x;
    if (n >= NN) return;
    atomicAdd(&g_cnt[batch[n]], 1.f);
}

__global__ void pool_div_k() {
    int idx = blockIdx.x * blockDim.x + threadIdx.x;
    if (idx >= GG * DD) return;
    int g = idx / DD;
    float c = g_cnt[g];
    g_pool[idx] = (c > 0.f) ? g_pool[idx] / c : 0.f;
}

// ---------------- launch -----------------------------------------------------
static inline int cdiv(int a, int b) { return (a + b - 1) / b; }

extern "C" void kernel_launch(void* const* d_in, const int* in_sizes, int n_in,
                              void* d_out, int out_size) {
    const int*   z        = (const int*)  d_in[0];
    const float* chi      = (const float*)d_in[1];
    const float* fc       = (const float*)d_in[2];
    const int*   ei       = (const int*)  d_in[3];
    const float* ea       = (const float*)d_in[4];
    const int*   batch    = (const int*)  d_in[5];
    const float* atom_emb = (const float*)d_in[6];
    const float* nap_w1   = (const float*)d_in[7];
    const float* nap_b1   = (const float*)d_in[8];
    const float* nap_w2   = (const float*)d_in[9];
    const float* nap_b2   = (const float*)d_in[10];
    const float* ee_w1    = (const float*)d_in[11];
    const float* ee_b1    = (const float*)d_in[12];
    const float* ee_w2    = (const float*)d_in[13];
    const float* ee_b2    = (const float*)d_in[14];
    const float* mlp_w1   = (const float*)d_in[15];
    const float* mlp_b1   = (const float*)d_in[16];
    const float* mlp_w2   = (const float*)d_in[17];
    const float* mlp_b2   = (const float*)d_in[18];
    const float* bn_gamma = (const float*)d_in[19];
    const float* bn_beta  = (const float*)d_in[20];
    const float* pool_w   = (const float*)d_in[21];
    const float* pool_b   = (const float*)d_in[22];
    float* out = (float*)d_out;

    float *ph, *pe, *pagg, *ptmp, *pout, *ppool;
    cudaGetSymbolAddress((void**)&ph,    g_h);
    cudaGetSymbolAddress((void**)&pe,    g_e);
    cudaGetSymbolAddress((void**)&pagg,  g_agg);
    cudaGetSymbolAddress((void**)&ptmp,  g_tmp);
    cudaGetSymbolAddress((void**)&pout,  g_out);
    cudaGetSymbolAddress((void**)&ppool, g_pool);

    const int TPB = 256;
    dim3 gemm_grid_N(cdiv(DD, BN), cdiv(NN, BM));
    dim3 gemm_grid_E(cdiv(DD, BN), cdiv(EE, BM));
    dim3 gemm_grid_G(cdiv(DD, BN), cdiv(GG, BM));

    // ---- node features: h0 = atom_emb[z] + MLP(node_attr); also seed agg = h0
    node_pre_k<<<cdiv(NN * DD, TPB), TPB>>>(chi, fc, nap_w1, nap_b1);
    gemm300_k<<<gemm_grid_N, 256>>>(ptmp, nap_w2, nap_b2, ph, pagg, NN, 0, atom_emb, z);

    // ---- edge features: e = MLP(edge_attr)
    edge_pre_k<<<cdiv(EE * DD, TPB), TPB>>>(ea, ee_w1, ee_b1);
    gemm300_k<<<gemm_grid_E, 256>>>(ptmp, ee_w2, ee_b2, pe, nullptr, EE, 0, nullptr, nullptr);

    // ---- L GINE layers
    for (int l = 0; l < LL; l++) {
        // agg already = h (seeded by prior epilogue); add sum_j relu(h[src]+e)
        msg_k<<<cdiv(EE * D4, TPB), TPB>>>(ei);
        gemm300_k<<<gemm_grid_N, 256>>>(pagg, mlp_w1 + (size_t)l * DD * DD, mlp_b1 + l * DD,
                                        ptmp, nullptr, NN, 1, nullptr, nullptr);
        gemm300_k<<<gemm_grid_N, 256>>>(ptmp, mlp_w2 + (size_t)l * DD * DD, mlp_b2 + l * DD,
                                        pout, nullptr, NN, 0, nullptr, nullptr);
        zero_stats_k<<<1, 2 * DD>>>();
        bn_stats_k<<<cdiv(NN, BN_ROWS), 320>>>();
        bn_apply_k<<<cdiv(NN * DD, TPB), TPB>>>(bn_gamma + l * DD, bn_beta + l * DD);
    }

    // ---- mean pool per graph + final projection
    pool_zero_k<<<cdiv(GG * DD, TPB), TPB>>>();
    pool_acc_k<<<cdiv(NN * D4, TPB), TPB>>>(batch);
    pool_cnt_k<<<cdiv(NN, TPB), TPB>>>(batch);
    pool_div_k<<<cdiv(GG * DD, TPB), TPB>>>();
    gemm300_k<<<gemm_grid_G, 256>>>(ppool, pool_w, pool_b, out, nullptr, GG, 0, nullptr, nullptr);
}

// round 5
// speedup vs baseline: 1.7236x; 1.1832x over previous
#include <cuda_runtime.h>
#include <cuda_bf16.h>
#include <cstdint>

#define NN 100000
#define EE 260000
#define DD 300
#define D4 75          // DD/4
#define LL 5
#define GG 4096
#define BN_EPS 1e-5f

// ---- HMMA GEMM geometry ----
#define BM   128       // block M tile
#define BNB  64        // block N tile
#define BKC  64        // K chunk per smem stage
#define KPAD 320       // padded K (5 chunks)
#define NPAD 320       // padded N (5 blocks of 64)
#define NCHK 5
#define NMAT 13

// smem stage layout (bytes): A hi | A lo | B hi | B lo
#define SA_H 0
#define SA_L 16384
#define SB_H 32768
#define SB_L 40960
#define STAGE 49152
#define SMEMSZ (2 * STAGE)   // 96 KB

// ---------------- scratch (device globals; no allocation allowed) ----------
__device__ __align__(16) float g_h  [(size_t)NN * DD];
__device__ __align__(16) float g_e  [(size_t)EE * DD];
__device__ __align__(16) float g_agg[(size_t)NN * DD];
__device__ __align__(16) float g_tmp[(size_t)EE * DD];
__device__ __align__(16) float g_out[(size_t)NN * DD];
__device__             float g_stats[2 * DD];
__device__ __align__(16) float g_pool[(size_t)GG * DD];
__device__             float g_cnt [GG];
// preconverted weights: [NMAT][NPAD rows(n)][KPAD cols(k)] bf16, hi and lo planes
__device__ __align__(16) __nv_bfloat16 g_wbh[(size_t)NMAT * NPAD * KPAD];
__device__ __align__(16) __nv_bfloat16 g_wbl[(size_t)NMAT * NPAD * KPAD];

// ---------------- helpers ----------------------------------------------------
__device__ __forceinline__ uint32_t smem_u32(const void* p) {
    uint32_t a;
    asm("{ .reg .u64 t; cvta.to.shared.u64 t, %1; cvt.u32.u64 %0, t; }" : "=r"(a) : "l"(p));
    return a;
}
__device__ __forceinline__ uint32_t swz(uint32_t off) { return off ^ ((off >> 3) & 0x70); }

__device__ __forceinline__ void ldsm4(uint32_t* r, uint32_t addr) {
    asm volatile("ldmatrix.sync.aligned.m8n8.x4.shared.b16 {%0,%1,%2,%3}, [%4];"
                 : "=r"(r[0]), "=r"(r[1]), "=r"(r[2]), "=r"(r[3]) : "r"(addr));
}
__device__ __forceinline__ void mma_bf16(float* d, const uint32_t* a, const uint32_t* b) {
    asm volatile(
        "mma.sync.aligned.m16n8k16.row.col.f32.bf16.bf16.f32 "
        "{%0,%1,%2,%3}, {%4,%5,%6,%7}, {%8,%9}, {%0,%1,%2,%3};"
        : "+f"(d[0]), "+f"(d[1]), "+f"(d[2]), "+f"(d[3])
        : "r"(a[0]), "r"(a[1]), "r"(a[2]), "r"(a[3]), "r"(b[0]), "r"(b[1]));
}

// ---------------- weight preconversion (13 mats -> bf16 hi/lo, [n][k], padded)
__global__ void wprep_k(const float* __restrict__ nap_w2, const float* __restrict__ ee_w2,
                        const float* __restrict__ mlp_w1, const float* __restrict__ mlp_w2,
                        const float* __restrict__ pool_w) {
    int idx = blockIdx.x * blockDim.x + threadIdx.x;
    if (idx >= NMAT * NPAD * KPAD) return;
    int mat = idx / (NPAD * KPAD);
    int rem = idx - mat * (NPAD * KPAD);
    int n = rem / KPAD, k = rem - n * KPAD;
    const float* W;
    if (mat == 0)      W = nap_w2;
    else if (mat == 1) W = ee_w2;
    else if (mat < 7)  W = mlp_w1 + (size_t)(mat - 2) * DD * DD;
    else if (mat < 12) W = mlp_w2 + (size_t)(mat - 7) * DD * DD;
    else               W = pool_w;
    float v = (n < DD && k < DD) ? W[(size_t)k * DD + n] : 0.f;
    __nv_bfloat16 hi = __float2bfloat16_rn(v);
    __nv_bfloat16 lo = __float2bfloat16_rn(v - __bfloat162float(hi));
    g_wbh[idx] = hi;
    g_wbl[idx] = lo;
}

// ---------------- HMMA GEMM: C[m,0:300] = act(A @ W + bias (+ gather)) -------
__global__ __launch_bounds__(256, 2)
void hgemm_k(const float* __restrict__ A,
             const __nv_bfloat16* __restrict__ Bh, const __nv_bfloat16* __restrict__ Bl,
             const float* __restrict__ bias, float* __restrict__ C,
             float* __restrict__ C2, int M, int relu,
             const float* __restrict__ gtab, const int* __restrict__ gidx) {
    extern __shared__ char smem[];
    const uint32_t sb = smem_u32(smem);
    const int tid  = threadIdx.x;
    const int lane = tid & 31;
    const int wid  = tid >> 5;
    const int warpM = wid & 3;        // 4 warps over M (32 rows each)
    const int warpN = wid >> 2;       // 2 warps over N (32 cols each)
    const int m0 = blockIdx.y * BM;
    const int n0 = blockIdx.x * BNB;

    // --- stage fill (global -> smem, A converted fp32 -> bf16 hi/lo)
    auto fill = [&](int c, int s) {
        char* st = smem + (s ? STAGE : 0);
        // A: 128 rows x 64 k
        {
            const int r = tid >> 1;
            const int half = tid & 1;
            const int gm = m0 + r;
            const float* arow = A + (size_t)gm * DD + c * BKC;
            #pragma unroll
            for (int i = 0; i < 8; i++) {
                const int kl = half * 32 + i * 4;
                float4 v = make_float4(0.f, 0.f, 0.f, 0.f);
                if (gm < M && c * BKC + kl + 4 <= DD)
                    v = *(const float4*)&arow[kl];
                __nv_bfloat16 h0 = __float2bfloat16_rn(v.x), h1 = __float2bfloat16_rn(v.y);
                __nv_bfloat16 h2 = __float2bfloat16_rn(v.z), h3 = __float2bfloat16_rn(v.w);
                __nv_bfloat16 l0 = __float2bfloat16_rn(v.x - __bfloat162float(h0));
                __nv_bfloat16 l1 = __float2bfloat16_rn(v.y - __bfloat162float(h1));
                __nv_bfloat16 l2 = __float2bfloat16_rn(v.z - __bfloat162float(h2));
                __nv_bfloat16 l3 = __float2bfloat16_rn(v.w - __bfloat162float(h3));
                uint32_t hA = (uint32_t)__bfloat16_as_ushort(h0) | ((uint32_t)__bfloat16_as_ushort(h1) << 16);
                uint32_t hB = (uint32_t)__bfloat16_as_ushort(h2) | ((uint32_t)__bfloat16_as_ushort(h3) << 16);
                uint32_t lA = (uint32_t)__bfloat16_as_ushort(l0) | ((uint32_t)__bfloat16_as_ushort(l1) << 16);
                uint32_t lB = (uint32_t)__bfloat16_as_ushort(l2) | ((uint32_t)__bfloat16_as_ushort(l3) << 16);
                const uint32_t so = swz(r * 128 + kl * 2);
                *(uint2*)(st + SA_H + so) = make_uint2(hA, hB);
                *(uint2*)(st + SA_L + so) = make_uint2(lA, lB);
            }
        }
        // B: 64 n-rows x 64 k (bf16 preconverted, padded -> no guards)
        {
            #pragma unroll
            for (int it = 0; it < 2; it++) {
                const int i = tid + it * 256;     // < 512
                const int n = i >> 3, ku = i & 7;
                const size_t go = (size_t)(n0 + n) * KPAD + c * BKC + ku * 8;
                uint4 vh = *(const uint4*)(Bh + go);
                uint4 vl = *(const uint4*)(Bl + go);
                const uint32_t so = swz(n * 128 + ku * 16);
                *(uint4*)(st + SB_H + so) = vh;
                *(uint4*)(st + SB_L + so) = vl;
            }
        }
    };

    float acc[2][4][4] = {};

    // ldmatrix lane geometry
    const int a_row = lane & 15;             // row within m16 tile
    const int a_kc  = (lane >> 4) * 8;       // 0 / 8
    const int b_row = (lane & 7) + ((lane & 16) ? 8 : 0);  // row within n16 group
    const int b_kc  = (lane & 8);            // 0 / 8

    fill(0, 0);
    __syncthreads();

    for (int c = 0; c < NCHK; c++) {
        const int s = c & 1;
        if (c + 1 < NCHK) fill(c + 1, s ^ 1);

        const uint32_t stb = sb + (s ? STAGE : 0);
        #pragma unroll
        for (int ks = 0; ks < 4; ks++) {
            const int k0 = ks * 16;
            uint32_t ah[2][4], al[2][4], bh[2][4], bl[2][4];
            #pragma unroll
            for (int mt = 0; mt < 2; mt++) {
                const uint32_t off = swz((warpM * 32 + mt * 16 + a_row) * 128 + (k0 + a_kc) * 2);
                ldsm4(ah[mt], stb + SA_H + off);
                ldsm4(al[mt], stb + SA_L + off);
            }
            #pragma unroll
            for (int g = 0; g < 2; g++) {
                const uint32_t off = swz((warpN * 32 + g * 16 + b_row) * 128 + (k0 + b_kc) * 2);
                ldsm4(bh[g], stb + SB_H + off);
                ldsm4(bl[g], stb + SB_L + off);
            }
            #pragma unroll
            for (int mt = 0; mt < 2; mt++) {
                #pragma unroll
                for (int nt = 0; nt < 4; nt++) {
                    const int g = nt >> 1, o = (nt & 1) * 2;
                    mma_bf16(acc[mt][nt], ah[mt], &bh[g][o]);
                    mma_bf16(acc[mt][nt], ah[mt], &bl[g][o]);
                    mma_bf16(acc[mt][nt], al[mt], &bh[g][o]);
                }
            }
        }
        __syncthreads();
    }

    // ---- epilogue: bias + optional gather + relu, dual-write
    const int er = lane >> 2;            // 0..7
    const int ec = (lane & 3) * 2;       // 0,2,4,6
    #pragma unroll
    for (int mt = 0; mt < 2; mt++) {
        #pragma unroll
        for (int rr = 0; rr < 2; rr++) {
            const int gm = m0 + warpM * 32 + mt * 16 + rr * 8 + er;
            if (gm >= M) continue;
            const float* grow = (gtab != nullptr) ? gtab + (size_t)gidx[gm] * DD : nullptr;
            float* crow  = C + (size_t)gm * DD;
            float* c2row = (C2 != nullptr) ? C2 + (size_t)gm * DD : nullptr;
            #pragma unroll
            for (int nt = 0; nt < 4; nt++) {
                const int n = n0 + warpN * 32 + nt * 8 + ec;
                if (n + 2 > DD) continue;
                float v0 = acc[mt][nt][rr * 2 + 0] + bias[n];
                float v1 = acc[mt][nt][rr * 2 + 1] + bias[n + 1];
                if (grow != nullptr) { v0 += grow[n]; v1 += grow[n + 1]; }
                if (relu) { v0 = fmaxf(v0, 0.f); v1 = fmaxf(v1, 0.f); }
                float2 v = make_float2(v0, v1);
                *(float2*)&crow[n] = v;
                if (c2row != nullptr) *(float2*)&c2row[n] = v;
            }
        }
    }
}

// ---------------- elementwise preambles ------------------------------------
__global__ void node_pre_k(const float* __restrict__ chi, const float* __restrict__ fc,
                           const float* __restrict__ w1, const float* __restrict__ b1) {
    int idx = blockIdx.x * blockDim.x + threadIdx.x;
    if (idx >= NN * DD) return;
    int n = idx / DD, d = idx - n * DD;
    float v = chi[n] * w1[d] + fc[n] * w1[DD + d] + b1[d];
    g_tmp[idx] = fmaxf(v, 0.f);
}

__global__ void edge_pre_k(const float* __restrict__ ea,
                           const float* __restrict__ w1, const float* __restrict__ b1) {
    int idx = blockIdx.x * blockDim.x + threadIdx.x;
    if (idx >= EE * DD) return;
    int e = idx / DD, d = idx - e * DD;
    float v = ea[e * 3 + 0] * w1[d] + ea[e * 3 + 1] * w1[DD + d]
            + ea[e * 3 + 2] * w1[2 * DD + d] + b1[d];
    g_tmp[idx] = fmaxf(v, 0.f);
}

// ---------------- message + scatter-add (agg preloaded with h) --------------
__global__ void msg_k(const int* __restrict__ ei) {
    int idx = blockIdx.x * blockDim.x + threadIdx.x;
    if (idx >= EE * D4) return;
    int e = idx / D4, j = idx - e * D4;
    int s = ei[e];
    int d = ei[EE + e];
    float4 hv = reinterpret_cast<const float4*>(g_h)[(size_t)s * D4 + j];
    float4 ev = reinterpret_cast<const float4*>(g_e)[(size_t)e * D4 + j];
    float x0 = fmaxf(hv.x + ev.x, 0.f);
    float x1 = fmaxf(hv.y + ev.y, 0.f);
    float x2 = fmaxf(hv.z + ev.z, 0.f);
    float x3 = fmaxf(hv.w + ev.w, 0.f);
    float* base = &g_agg[(size_t)d * DD + j * 4];
    atomicAdd(base + 0, x0);
    atomicAdd(base + 1, x1);
    atomicAdd(base + 2, x2);
    atomicAdd(base + 3, x3);
}

// ---------------- batchnorm --------------------------------------------------
__global__ void zero_stats_k() {
    int i = threadIdx.x;
    if (i < 2 * DD) g_stats[i] = 0.f;
}

#define BN_ROWS 512
__global__ void bn_stats_k() {
    int d = threadIdx.x;
    if (d >= DD) return;
    int r0 = blockIdx.x * BN_ROWS;
    int r1 = r0 + BN_ROWS; if (r1 > NN) r1 = NN;
    float s = 0.f, s2 = 0.f;
    int r = r0;
    for (; r + 4 <= r1; r += 4) {
        float v0 = g_out[(size_t)(r + 0) * DD + d];
        float v1 = g_out[(size_t)(r + 1) * DD + d];
        float v2 = g_out[(size_t)(r + 2) * DD + d];
        float v3 = g_out[(size_t)(r + 3) * DD + d];
        s  += (v0 + v1) + (v2 + v3);
        s2 += (v0 * v0 + v1 * v1) + (v2 * v2 + v3 * v3);
    }
    for (; r < r1; r++) {
        float v = g_out[(size_t)r * DD + d];
        s += v; s2 += v * v;
    }
    atomicAdd(&g_stats[d], s);
    atomicAdd(&g_stats[DD + d], s2);
}

__global__ void bn_apply_k(const float* __restrict__ gamma, const float* __restrict__ beta) {
    int idx = blockIdx.x * blockDim.x + threadIdx.x;
    if (idx >= NN * DD) return;
    int d = idx % DD;
    const float invN = 1.f / (float)NN;
    float mean = g_stats[d] * invN;
    float var  = g_stats[DD + d] * invN - mean * mean;
    float v = gamma[d] * (g_out[idx] - mean) * rsqrtf(var + BN_EPS) + beta[d];
    v = fmaxf(v, 0.f);
    g_h[idx]   = v;
    g_agg[idx] = v;
}

// ---------------- pooling ----------------------------------------------------
__global__ void pool_zero_k() {
    int idx = blockIdx.x * blockDim.x + threadIdx.x;
    if (idx < GG * DD) g_pool[idx] = 0.f;
    if (idx < GG) g_cnt[idx] = 0.f;
}

__global__ void pool_acc_k(const int* __restrict__ batch) {
    int idx = blockIdx.x * blockDim.x + threadIdx.x;
    if (idx >= NN * D4) return;
    int n = idx / D4, j = idx - n * D4;
    int g = batch[n];
    float4 v = reinterpret_cast<const float4*>(g_h)[(size_t)n * D4 + j];
    float* base = &g_pool[(size_t)g * DD + j * 4];
    atomicAdd(base + 0, v.x);
    atomicAdd(base + 1, v.y);
    atomicAdd(base + 2, v.z);
    atomicAdd(base + 3, v.w);
}

__global__ void pool_cnt_k(const int* __restrict__ batch) {
    int n = blockIdx.x * blockDim.x + threadIdx.x;
    if (n >= NN) return;
    atomicAdd(&g_cnt[batch[n]], 1.f);
}

__global__ void pool_div_k() {
    int idx = blockIdx.x * blockDim.x + threadIdx.x;
    if (idx >= GG * DD) return;
    int g = idx / DD;
    float c = g_cnt[g];
    g_pool[idx] = (c > 0.f) ? g_pool[idx] / c : 0.f;
}

// ---------------- launch -----------------------------------------------------
static inline int cdiv(int a, int b) { return (a + b - 1) / b; }

extern "C" void kernel_launch(void* const* d_in, const int* in_sizes, int n_in,
                              void* d_out, int out_size) {
    const int*   z        = (const int*)  d_in[0];
    const float* chi      = (const float*)d_in[1];
    const float* fc       = (const float*)d_in[2];
    const int*   ei       = (const int*)  d_in[3];
    const float* ea       = (const float*)d_in[4];
    const int*   batch    = (const int*)  d_in[5];
    const float* atom_emb = (const float*)d_in[6];
    const float* nap_w1   = (const float*)d_in[7];
    const float* nap_b1   = (const float*)d_in[8];
    const float* nap_w2   = (const float*)d_in[9];
    const float* nap_b2   = (const float*)d_in[10];
    const float* ee_w1    = (const float*)d_in[11];
    const float* ee_b1    = (const float*)d_in[12];
    const float* ee_w2    = (const float*)d_in[13];
    const float* ee_b2    = (const float*)d_in[14];
    const float* mlp_w1   = (const float*)d_in[15];
    const float* mlp_b1   = (const float*)d_in[16];
    const float* mlp_w2   = (const float*)d_in[17];
    const float* mlp_b2   = (const float*)d_in[18];
    const float* bn_gamma = (const float*)d_in[19];
    const float* bn_beta  = (const float*)d_in[20];
    const float* pool_w   = (const float*)d_in[21];
    const float* pool_b   = (const float*)d_in[22];
    float* out = (float*)d_out;

    float *ph, *pe, *pagg, *ptmp, *pout, *ppool;
    __nv_bfloat16 *pwh, *pwl;
    cudaGetSymbolAddress((void**)&ph,    g_h);
    cudaGetSymbolAddress((void**)&pe,    g_e);
    cudaGetSymbolAddress((void**)&pagg,  g_agg);
    cudaGetSymbolAddress((void**)&ptmp,  g_tmp);
    cudaGetSymbolAddress((void**)&pout,  g_out);
    cudaGetSymbolAddress((void**)&ppool, g_pool);
    cudaGetSymbolAddress((void**)&pwh,   g_wbh);
    cudaGetSymbolAddress((void**)&pwl,   g_wbl);

    cudaFuncSetAttribute(hgemm_k, cudaFuncAttributeMaxDynamicSharedMemorySize, SMEMSZ);

    const int TPB = 256;
    const size_t WSTRIDE = (size_t)NPAD * KPAD;
    #define WH(m) (pwh + (size_t)(m) * WSTRIDE)
    #define WL(m) (pwl + (size_t)(m) * WSTRIDE)

    dim3 grid_N(NPAD / BNB, cdiv(NN, BM));
    dim3 grid_E(NPAD / BNB, cdiv(EE, BM));
    dim3 grid_G(NPAD / BNB, cdiv(GG, BM));

    // ---- preconvert all weight matrices to bf16 hi/lo (K-major, padded)
    wprep_k<<<cdiv(NMAT * NPAD * KPAD, TPB), TPB>>>(nap_w2, ee_w2, mlp_w1, mlp_w2, pool_w);

    // ---- node features: h0 = atom_emb[z] + MLP(node_attr); seed agg = h0
    node_pre_k<<<cdiv(NN * DD, TPB), TPB>>>(chi, fc, nap_w1, nap_b1);
    hgemm_k<<<grid_N, 256, SMEMSZ>>>(ptmp, WH(0), WL(0), nap_b2, ph, pagg, NN, 0, atom_emb, z);

    // ---- edge features: e = MLP(edge_attr)
    edge_pre_k<<<cdiv(EE * DD, TPB), TPB>>>(ea, ee_w1, ee_b1);
    hgemm_k<<<grid_E, 256, SMEMSZ>>>(ptmp, WH(1), WL(1), ee_b2, pe, nullptr, EE, 0, nullptr, nullptr);

    // ---- L GINE layers
    for (int l = 0; l < LL; l++) {
        msg_k<<<cdiv(EE * D4, TPB), TPB>>>(ei);
        hgemm_k<<<grid_N, 256, SMEMSZ>>>(pagg, WH(2 + l), WL(2 + l), mlp_b1 + l * DD,
                                         ptmp, nullptr, NN, 1, nullptr, nullptr);
        hgemm_k<<<grid_N, 256, SMEMSZ>>>(ptmp, WH(7 + l), WL(7 + l), mlp_b2 + l * DD,
                                         pout, nullptr, NN, 0, nullptr, nullptr);
        zero_stats_k<<<1, 2 * DD>>>();
        bn_stats_k<<<cdiv(NN, BN_ROWS), 320>>>();
        bn_apply_k<<<cdiv(NN * DD, TPB), TPB>>>(bn_gamma + l * DD, bn_beta + l * DD);
    }

    // ---- mean pool per graph + final projection
    pool_zero_k<<<cdiv(GG * DD, TPB), TPB>>>();
    pool_acc_k<<<cdiv(NN * D4, TPB), TPB>>>(batch);
    pool_cnt_k<<<cdiv(NN, TPB), TPB>>>(batch);
    pool_div_k<<<cdiv(GG * DD, TPB), TPB>>>();
    hgemm_k<<<grid_G, 256, SMEMSZ>>>(ppool, WH(12), WL(12), pool_b, out, nullptr, GG, 0, nullptr, nullptr);
}